// round 10
// baseline (speedup 1.0000x reference)
#include <cuda_runtime.h>
#include <cuda_fp16.h>

// Critic_66511863546286 — folded attention critic, round 10.
// B=256, S=1024, H=256, feat dims = 2, 3 iterations.
// R10 = R9 with (a) poly-tanh ratio raised 25% -> 50% (MUFU 96->64 cyc/group,
// FMA ~83 measured-scale becomes the binder) and (b) split accumulators:
// MUFU-tanh results and poly-tanh results accumulate into separate half2
// registers per point, halving the serialized hfma2 RAW chain.

#define NB 256
#define NS 1024
#define NH 256
#define NHP 128   // h-pairs
#define K3 768
#define NITER 3
#define NFC 20
#define BT 512    // thread t owns points t (lo) and t+512 (hi)

// Precomputed fused coefficients (natural scale, f32 masters).
__device__ float4 gABp[NH];  // (A0, A1, B0, B1) per h
__device__ float4 gCdv[NH];  // (C0, C1, d, v[h])
__device__ float2 gF[NFC];   // fc1_w · sw
__device__ float  gfb[NFC];  // fc1_w · sb + fc1_b

__device__ __forceinline__ float ex2_approx(float x) {
    float y; asm("ex2.approx.f32 %0, %1;" : "=f"(y) : "f"(x)); return y;
}
__device__ __forceinline__ unsigned hfma2u(unsigned a, unsigned b, unsigned c) {
    unsigned d;
    asm("fma.rn.f16x2 %0, %1, %2, %3;" : "=r"(d) : "r"(a), "r"(b), "r"(c));
    return d;
}
__device__ __forceinline__ unsigned hmul2u(unsigned a, unsigned b) {
    unsigned d;
    asm("mul.rn.f16x2 %0, %1, %2;" : "=r"(d) : "r"(a), "r"(b));
    return d;
}
__device__ __forceinline__ unsigned hadd2u(unsigned a, unsigned b) {
    unsigned d;
    asm("add.rn.f16x2 %0, %1, %2;" : "=r"(d) : "r"(a), "r"(b));
    return d;
}
__device__ __forceinline__ unsigned tanh16x2(unsigned x) {
    unsigned y; asm("tanh.approx.f16x2 %0, %1;" : "=r"(y) : "r"(x)); return y;
}
__device__ __forceinline__ unsigned f2h2(float a, float b) {
    __half2 h = __floats2half2_rn(a, b);
    return *reinterpret_cast<unsigned*>(&h);
}
__device__ __forceinline__ float h2sum(unsigned u) {
    __half2 h = *reinterpret_cast<__half2*>(&u);
    float2 f = __half22float2(h);
    return f.x + f.y;
}

// ---------------------------------------------------------------------------
// Precompute: fold W through the 1x1-conv encoders (f32 masters).
// ---------------------------------------------------------------------------
__global__ void precompute_kernel(
    const float* __restrict__ sw, const float* __restrict__ sb,
    const float* __restrict__ dw, const float* __restrict__ db,
    const float* __restrict__ W,  const float* __restrict__ v,
    const float* __restrict__ fc1_w, const float* __restrict__ fc1_b)
{
    __shared__ float sred[8][8];
    int tid = threadIdx.x;
    int blk = blockIdx.x;
    int lane = tid & 31, w = tid >> 5;

    if (blk < NH) {
        int h = blk;
        float ws = W[h * K3 + tid];
        float wd = W[h * K3 + 256 + tid];
        float wc = W[h * K3 + 512 + tid];
        float s0 = sw[tid * 2 + 0], s1 = sw[tid * 2 + 1];
        float sbk = sb[tid];
        float p[7];
        p[0] = ws * s0;
        p[1] = ws * s1;
        p[2] = wd * dw[tid * 2 + 0];
        p[3] = wd * dw[tid * 2 + 1];
        p[4] = wc * s0;
        p[5] = wc * s1;
        p[6] = ws * sbk + wd * db[tid] + wc * sbk;
        #pragma unroll
        for (int o = 16; o > 0; o >>= 1)
            #pragma unroll
            for (int i = 0; i < 7; i++)
                p[i] += __shfl_xor_sync(0xffffffffu, p[i], o);
        if (lane == 0) {
            #pragma unroll
            for (int i = 0; i < 7; i++) sred[w][i] = p[i];
        }
        __syncthreads();
        if (tid == 0) {
            float q[7];
            #pragma unroll
            for (int i = 0; i < 7; i++) {
                q[i] = 0.f;
                for (int ww = 0; ww < 8; ww++) q[i] += sred[ww][i];
            }
            gABp[h] = make_float4(q[0], q[1], q[2], q[3]);
            gCdv[h] = make_float4(q[4], q[5], q[6], v[h]);
        }
    } else {
        int j = blk - NH;
        float fw = fc1_w[j * NH + tid];
        float p0 = fw * sw[tid * 2 + 0];
        float p1 = fw * sw[tid * 2 + 1];
        float p2 = fw * sb[tid];
        #pragma unroll
        for (int o = 16; o > 0; o >>= 1) {
            p0 += __shfl_xor_sync(0xffffffffu, p0, o);
            p1 += __shfl_xor_sync(0xffffffffu, p1, o);
            p2 += __shfl_xor_sync(0xffffffffu, p2, o);
        }
        if (lane == 0) { sred[w][0] = p0; sred[w][1] = p1; sred[w][2] = p2; }
        __syncthreads();
        if (tid == 0) {
            float q0 = 0.f, q1 = 0.f, q2 = 0.f;
            for (int ww = 0; ww < 8; ww++) {
                q0 += sred[ww][0]; q1 += sred[ww][1]; q2 += sred[ww][2];
            }
            gF[j] = make_float2(q0, q1);
            gfb[j] = q2 + fc1_b[j];
        }
    }
}

// ---------------------------------------------------------------------------
// Main kernel: one block per batch; 512 threads; thread t owns points
// t (lo) and t+512 (hi); h in f16x2 pairs, full half2 inner chain.
// Alternating h-pair iterations: MUFU tanh / FMA-pipe polynomial tanh,
// each with its own accumulator (shorter RAW chains).
// ---------------------------------------------------------------------------
__global__ void __launch_bounds__(BT, 2)
attn_kernel(const float* __restrict__ stat, const float* __restrict__ dyn,
            const float* __restrict__ istate,
            const float* __restrict__ fc2_w, const float* __restrict__ fc2_b,
            float* __restrict__ out)
{
    __shared__ uint4 sC[NHP];        // (A0pair, A1pair, B0pair, B1pair) half2s
    __shared__ uint2 sGV[NHP];       // (g-pair, v-pair) half2s, g rewritten/iter
    __shared__ float4 sCdv[NH];      // (C0,C1,d,v) f32
    __shared__ float sredM[16], sredP[16], sredX[16], sredY[16];
    __shared__ float bc[4];

    const float LOG2E = 1.4426950408889634f;
    int b = blockIdx.x;
    int s = threadIdx.x;              // 0..511
    int lane = s & 31, warp = s >> 5;

    // odd-quintic tanh: tanh(x) ~= x*(1 + x2*(PA + PB*x2))
    const unsigned PA2 = f2h2(-0.3248f, -0.3248f);
    const unsigned PB2 = f2h2(0.0864f, 0.0864f);
    const unsigned ONE2 = f2h2(1.0f, 1.0f);

    // features for points s (lo) and s+512 (hi)
    float x0l = stat[b * 2 * NS + s],      x0h = stat[b * 2 * NS + s + BT];
    float x1l = stat[b * 2 * NS + NS + s], x1h = stat[b * 2 * NS + NS + s + BT];
    float y0l = dyn[b * 2 * NS + s],       y0h = dyn[b * 2 * NS + s + BT];
    float y1l = dyn[b * 2 * NS + NS + s],  y1h = dyn[b * 2 * NS + NS + s + BT];
    unsigned x0l2 = f2h2(x0l, x0l), x0h2 = f2h2(x0h, x0h);
    unsigned x1l2 = f2h2(x1l, x1l), x1h2 = f2h2(x1h, x1h);
    unsigned y0l2 = f2h2(y0l, y0l), y0h2 = f2h2(y0h, y0h);
    unsigned y1l2 = f2h2(y1l, y1l), y1h2 = f2h2(y1h, y1h);

    if (s < NH) sCdv[s] = gCdv[s];
    if (s < NHP) {
        float4 pa = gABp[2 * s];
        float4 pb = gABp[2 * s + 1];
        sC[s] = make_uint4(f2h2(pa.x, pb.x), f2h2(pa.y, pb.y),
                           f2h2(pa.z, pb.z), f2h2(pa.w, pb.w));
    }

    float z0 = istate[b * 2 + 0];
    float z1 = istate[b * 2 + 1];

    for (int it = 0; it < NITER; it++) {
        __syncthreads();
        if (s < NHP) {
            float4 ca = sCdv[2 * s];
            float4 cb = sCdv[2 * s + 1];
            float ga = fmaf(ca.x, z0, fmaf(ca.y, z1, ca.z));
            float gb = fmaf(cb.x, z0, fmaf(cb.y, z1, cb.z));
            sGV[s] = make_uint2(f2h2(ga, gb), f2h2(ca.w, cb.w));
        }
        __syncthreads();

        // scores: per point, t = sum over h-pairs of (v,v')*tanh(A·x+B·y+(g,g'))
        // Even j -> MUFU tanh into acc*0; odd j -> poly tanh into acc*1.
        float t0 = 0.f, t1 = 0.f;
        #pragma unroll
        for (int kc = 0; kc < NHP / 16; kc++) {
            unsigned accl0 = 0u, accl1 = 0u, acch0 = 0u, acch1 = 0u;
            #pragma unroll
            for (int j = 0; j < 16; j++) {
                int k = kc * 16 + j;
                uint4 cc = sC[k];            // LDS.128
                uint2 gv = sGV[k];           // LDS.64

                unsigned argl = hfma2u(cc.x, x0l2, gv.x);
                argl = hfma2u(cc.y, x1l2, argl);
                argl = hfma2u(cc.z, y0l2, argl);
                argl = hfma2u(cc.w, y1l2, argl);

                unsigned argh = hfma2u(cc.x, x0h2, gv.x);
                argh = hfma2u(cc.y, x1h2, argh);
                argh = hfma2u(cc.z, y0h2, argh);
                argh = hfma2u(cc.w, y1h2, argh);

                if (j & 1) {
                    // FMA-pipe polynomial tanh
                    unsigned x2l = hmul2u(argl, argl);
                    unsigned ul = hfma2u(x2l, PB2, PA2);
                    unsigned wl = hfma2u(ul, x2l, ONE2);
                    unsigned thl = hmul2u(wl, argl);
                    unsigned x2h = hmul2u(argh, argh);
                    unsigned uh = hfma2u(x2h, PB2, PA2);
                    unsigned wh = hfma2u(uh, x2h, ONE2);
                    unsigned thh = hmul2u(wh, argh);
                    accl1 = hfma2u(gv.y, thl, accl1);
                    acch1 = hfma2u(gv.y, thh, acch1);
                } else {
                    accl0 = hfma2u(gv.y, tanh16x2(argl), accl0);
                    acch0 = hfma2u(gv.y, tanh16x2(argh), acch0);
                }
            }
            t0 += h2sum(hadd2u(accl0, accl1));
            t1 += h2sum(hadd2u(acch0, acch1));
        }

        // block max over all 1024 points
        float m = fmaxf(t0, t1);
        #pragma unroll
        for (int o = 16; o > 0; o >>= 1)
            m = fmaxf(m, __shfl_xor_sync(0xffffffffu, m, o));
        if (lane == 0) sredM[warp] = m;
        __syncthreads();
        if (s < 16) {
            float mm = sredM[s];
            #pragma unroll
            for (int o = 8; o > 0; o >>= 1)
                mm = fmaxf(mm, __shfl_xor_sync(0xffffu, mm, o));
            if (s == 0) bc[0] = mm;
        }
        __syncthreads();
        float M = bc[0];

        // softmax weights + weighted feature sums (all f32)
        float p0 = ex2_approx((t0 - M) * LOG2E);
        float p1 = ex2_approx((t1 - M) * LOG2E);
        float a  = p0 + p1;
        float bx = fmaf(p0, x0l, p1 * x0h);
        float by = fmaf(p0, x1l, p1 * x1h);
        #pragma unroll
        for (int o = 16; o > 0; o >>= 1) {
            a  += __shfl_xor_sync(0xffffffffu, a,  o);
            bx += __shfl_xor_sync(0xffffffffu, bx, o);
            by += __shfl_xor_sync(0xffffffffu, by, o);
        }
        if (lane == 0) { sredP[warp] = a; sredX[warp] = bx; sredY[warp] = by; }
        __syncthreads();
        if (s < 16) {
            float aa = sredP[s], xx = sredX[s], yy = sredY[s];
            #pragma unroll
            for (int o = 8; o > 0; o >>= 1) {
                aa += __shfl_xor_sync(0xffffu, aa, o);
                xx += __shfl_xor_sync(0xffffu, xx, o);
                yy += __shfl_xor_sync(0xffffu, yy, o);
            }
            if (s == 0) { bc[1] = aa; bc[2] = xx; bc[3] = yy; }
        }
        __syncthreads();
        float inv = 1.f / bc[1];
        z0 = bc[2] * inv;   // xbar0
        z1 = bc[3] * inv;   // xbar1
    }

    // Output MLP (folded through sw), f32
    if (s == 0) {
        float o = fc2_b[0];
        #pragma unroll
        for (int j = 0; j < NFC; j++) {
            float hv = fmaf(gF[j].x, z0, fmaf(gF[j].y, z1, gfb[j]));
            hv = fmaxf(hv, 0.f);
            o = fmaf(fc2_w[j], hv, o);
        }
        out[b] = o;
    }
}

extern "C" void kernel_launch(void* const* d_in, const int* in_sizes, int n_in,
                              void* d_out, int out_size)
{
    const float* stat   = (const float*)d_in[0];   // [256, 2, 1024]
    const float* dyn    = (const float*)d_in[1];   // [256, 2, 1024]
    const float* istate = (const float*)d_in[2];   // [256, 2]
    const float* sw     = (const float*)d_in[3];   // [256, 2]
    const float* sb     = (const float*)d_in[4];   // [256]
    const float* dw     = (const float*)d_in[5];   // [256, 2]
    const float* db     = (const float*)d_in[6];   // [256]
    const float* v      = (const float*)d_in[7];   // [1, 256]
    const float* W      = (const float*)d_in[8];   // [256, 768]
    const float* fc1_w  = (const float*)d_in[9];   // [20, 256]
    const float* fc1_b  = (const float*)d_in[10];  // [20]
    const float* fc2_w  = (const float*)d_in[11];  // [1, 20]
    const float* fc2_b  = (const float*)d_in[12];  // [1]
    float* out = (float*)d_out;                    // [256, 1]

    precompute_kernel<<<NH + NFC, 256>>>(sw, sb, dw, db, W, v, fc1_w, fc1_b);
    attn_kernel<<<NB, BT>>>(stat, dyn, istate, fc2_w, fc2_b, out);
}

// round 11
// speedup vs baseline: 1.0120x; 1.0120x over previous
#include <cuda_runtime.h>
#include <cuda_fp16.h>

// Critic_66511863546286 — folded attention critic, round 11.
// B=256, S=1024, H=256, feat dims = 2, 3 iterations.
// R11 = R9 (f=1/4 poly — measured MUFU/FMA balance point for rt16 tanh16x2)
//  + split accumulators (MUFU-tanh vs poly-tanh results accumulate into
//    separate half2 regs; halves the serialized RAW chain)
//  + occupancy 3 blocks/SM via __launch_bounds__(512,3) (regs capped at 42;
//    12 warps/SMSP instead of 8 to close the 25% latency-stall gap measured
//    in R9/R10 where no pipe exceeded 66%).

#define NB 256
#define NS 1024
#define NH 256
#define NHP 128   // h-pairs
#define K3 768
#define NITER 3
#define NFC 20
#define BT 512    // thread t owns points t (lo) and t+512 (hi)

// Precomputed fused coefficients (natural scale, f32 masters).
__device__ float4 gABp[NH];  // (A0, A1, B0, B1) per h
__device__ float4 gCdv[NH];  // (C0, C1, d, v[h])
__device__ float2 gF[NFC];   // fc1_w · sw
__device__ float  gfb[NFC];  // fc1_w · sb + fc1_b

__device__ __forceinline__ float ex2_approx(float x) {
    float y; asm("ex2.approx.f32 %0, %1;" : "=f"(y) : "f"(x)); return y;
}
__device__ __forceinline__ unsigned hfma2u(unsigned a, unsigned b, unsigned c) {
    unsigned d;
    asm("fma.rn.f16x2 %0, %1, %2, %3;" : "=r"(d) : "r"(a), "r"(b), "r"(c));
    return d;
}
__device__ __forceinline__ unsigned hmul2u(unsigned a, unsigned b) {
    unsigned d;
    asm("mul.rn.f16x2 %0, %1, %2;" : "=r"(d) : "r"(a), "r"(b));
    return d;
}
__device__ __forceinline__ unsigned hadd2u(unsigned a, unsigned b) {
    unsigned d;
    asm("add.rn.f16x2 %0, %1, %2;" : "=r"(d) : "r"(a), "r"(b));
    return d;
}
__device__ __forceinline__ unsigned tanh16x2(unsigned x) {
    unsigned y; asm("tanh.approx.f16x2 %0, %1;" : "=r"(y) : "r"(x)); return y;
}
__device__ __forceinline__ unsigned f2h2(float a, float b) {
    __half2 h = __floats2half2_rn(a, b);
    return *reinterpret_cast<unsigned*>(&h);
}
__device__ __forceinline__ float h2sum(unsigned u) {
    __half2 h = *reinterpret_cast<__half2*>(&u);
    float2 f = __half22float2(h);
    return f.x + f.y;
}

// ---------------------------------------------------------------------------
// Precompute: fold W through the 1x1-conv encoders (f32 masters).
// ---------------------------------------------------------------------------
__global__ void precompute_kernel(
    const float* __restrict__ sw, const float* __restrict__ sb,
    const float* __restrict__ dw, const float* __restrict__ db,
    const float* __restrict__ W,  const float* __restrict__ v,
    const float* __restrict__ fc1_w, const float* __restrict__ fc1_b)
{
    __shared__ float sred[8][8];
    int tid = threadIdx.x;
    int blk = blockIdx.x;
    int lane = tid & 31, w = tid >> 5;

    if (blk < NH) {
        int h = blk;
        float ws = W[h * K3 + tid];
        float wd = W[h * K3 + 256 + tid];
        float wc = W[h * K3 + 512 + tid];
        float s0 = sw[tid * 2 + 0], s1 = sw[tid * 2 + 1];
        float sbk = sb[tid];
        float p[7];
        p[0] = ws * s0;
        p[1] = ws * s1;
        p[2] = wd * dw[tid * 2 + 0];
        p[3] = wd * dw[tid * 2 + 1];
        p[4] = wc * s0;
        p[5] = wc * s1;
        p[6] = ws * sbk + wd * db[tid] + wc * sbk;
        #pragma unroll
        for (int o = 16; o > 0; o >>= 1)
            #pragma unroll
            for (int i = 0; i < 7; i++)
                p[i] += __shfl_xor_sync(0xffffffffu, p[i], o);
        if (lane == 0) {
            #pragma unroll
            for (int i = 0; i < 7; i++) sred[w][i] = p[i];
        }
        __syncthreads();
        if (tid == 0) {
            float q[7];
            #pragma unroll
            for (int i = 0; i < 7; i++) {
                q[i] = 0.f;
                for (int ww = 0; ww < 8; ww++) q[i] += sred[ww][i];
            }
            gABp[h] = make_float4(q[0], q[1], q[2], q[3]);
            gCdv[h] = make_float4(q[4], q[5], q[6], v[h]);
        }
    } else {
        int j = blk - NH;
        float fw = fc1_w[j * NH + tid];
        float p0 = fw * sw[tid * 2 + 0];
        float p1 = fw * sw[tid * 2 + 1];
        float p2 = fw * sb[tid];
        #pragma unroll
        for (int o = 16; o > 0; o >>= 1) {
            p0 += __shfl_xor_sync(0xffffffffu, p0, o);
            p1 += __shfl_xor_sync(0xffffffffu, p1, o);
            p2 += __shfl_xor_sync(0xffffffffu, p2, o);
        }
        if (lane == 0) { sred[w][0] = p0; sred[w][1] = p1; sred[w][2] = p2; }
        __syncthreads();
        if (tid == 0) {
            float q0 = 0.f, q1 = 0.f, q2 = 0.f;
            for (int ww = 0; ww < 8; ww++) {
                q0 += sred[ww][0]; q1 += sred[ww][1]; q2 += sred[ww][2];
            }
            gF[j] = make_float2(q0, q1);
            gfb[j] = q2 + fc1_b[j];
        }
    }
}

// ---------------------------------------------------------------------------
// Main kernel: one block per batch; 512 threads; thread t owns points
// t (lo) and t+512 (hi); h in f16x2 pairs, full half2 inner chain.
// 3/4 of h-pair iterations: MUFU tanh (-> acc*0); 1/4: FMA-pipe poly (-> acc*1).
// ---------------------------------------------------------------------------
__global__ void __launch_bounds__(BT, 3)
attn_kernel(const float* __restrict__ stat, const float* __restrict__ dyn,
            const float* __restrict__ istate,
            const float* __restrict__ fc2_w, const float* __restrict__ fc2_b,
            float* __restrict__ out)
{
    __shared__ uint4 sC[NHP];        // (A0pair, A1pair, B0pair, B1pair) half2s
    __shared__ uint2 sGV[NHP];       // (g-pair, v-pair) half2s, g rewritten/iter
    __shared__ float4 sCdv[NH];      // (C0,C1,d,v) f32
    __shared__ float sredM[16], sredP[16], sredX[16], sredY[16];
    __shared__ float bc[4];

    const float LOG2E = 1.4426950408889634f;
    int b = blockIdx.x;
    int s = threadIdx.x;              // 0..511
    int lane = s & 31, warp = s >> 5;

    // odd-quintic tanh: tanh(x) ~= x*(1 + x2*(PA + PB*x2))
    const unsigned PA2 = f2h2(-0.3248f, -0.3248f);
    const unsigned PB2 = f2h2(0.0864f, 0.0864f);
    const unsigned ONE2 = f2h2(1.0f, 1.0f);

    // features for points s (lo) and s+512 (hi)
    float x0l = stat[b * 2 * NS + s],      x0h = stat[b * 2 * NS + s + BT];
    float x1l = stat[b * 2 * NS + NS + s], x1h = stat[b * 2 * NS + NS + s + BT];
    float y0l = dyn[b * 2 * NS + s],       y0h = dyn[b * 2 * NS + s + BT];
    float y1l = dyn[b * 2 * NS + NS + s],  y1h = dyn[b * 2 * NS + NS + s + BT];
    unsigned x0l2 = f2h2(x0l, x0l), x0h2 = f2h2(x0h, x0h);
    unsigned x1l2 = f2h2(x1l, x1l), x1h2 = f2h2(x1h, x1h);
    unsigned y0l2 = f2h2(y0l, y0l), y0h2 = f2h2(y0h, y0h);
    unsigned y1l2 = f2h2(y1l, y1l), y1h2 = f2h2(y1h, y1h);

    if (s < NH) sCdv[s] = gCdv[s];
    if (s < NHP) {
        float4 pa = gABp[2 * s];
        float4 pb = gABp[2 * s + 1];
        sC[s] = make_uint4(f2h2(pa.x, pb.x), f2h2(pa.y, pb.y),
                           f2h2(pa.z, pb.z), f2h2(pa.w, pb.w));
    }

    float z0 = istate[b * 2 + 0];
    float z1 = istate[b * 2 + 1];

    for (int it = 0; it < NITER; it++) {
        __syncthreads();
        if (s < NHP) {
            float4 ca = sCdv[2 * s];
            float4 cb = sCdv[2 * s + 1];
            float ga = fmaf(ca.x, z0, fmaf(ca.y, z1, ca.z));
            float gb = fmaf(cb.x, z0, fmaf(cb.y, z1, cb.z));
            sGV[s] = make_uint2(f2h2(ga, gb), f2h2(ca.w, cb.w));
        }
        __syncthreads();

        // scores: per point, t = sum over h-pairs of (v,v')*tanh(A·x+B·y+(g,g'))
        // j%4==3 -> poly tanh into acc*1; else MUFU tanh into acc*0.
        float t0 = 0.f, t1 = 0.f;
        #pragma unroll
        for (int kc = 0; kc < NHP / 16; kc++) {
            unsigned accl0 = 0u, accl1 = 0u, acch0 = 0u, acch1 = 0u;
            #pragma unroll
            for (int j = 0; j < 16; j++) {
                int k = kc * 16 + j;
                uint4 cc = sC[k];            // LDS.128
                uint2 gv = sGV[k];           // LDS.64

                unsigned argl = hfma2u(cc.x, x0l2, gv.x);
                argl = hfma2u(cc.y, x1l2, argl);
                argl = hfma2u(cc.z, y0l2, argl);
                argl = hfma2u(cc.w, y1l2, argl);

                unsigned argh = hfma2u(cc.x, x0h2, gv.x);
                argh = hfma2u(cc.y, x1h2, argh);
                argh = hfma2u(cc.z, y0h2, argh);
                argh = hfma2u(cc.w, y1h2, argh);

                if ((j & 3) == 3) {
                    // FMA-pipe polynomial tanh
                    unsigned x2l = hmul2u(argl, argl);
                    unsigned ul = hfma2u(x2l, PB2, PA2);
                    unsigned wl = hfma2u(ul, x2l, ONE2);
                    unsigned thl = hmul2u(wl, argl);
                    unsigned x2h = hmul2u(argh, argh);
                    unsigned uh = hfma2u(x2h, PB2, PA2);
                    unsigned wh = hfma2u(uh, x2h, ONE2);
                    unsigned thh = hmul2u(wh, argh);
                    accl1 = hfma2u(gv.y, thl, accl1);
                    acch1 = hfma2u(gv.y, thh, acch1);
                } else {
                    accl0 = hfma2u(gv.y, tanh16x2(argl), accl0);
                    acch0 = hfma2u(gv.y, tanh16x2(argh), acch0);
                }
            }
            t0 += h2sum(hadd2u(accl0, accl1));
            t1 += h2sum(hadd2u(acch0, acch1));
        }

        // block max over all 1024 points
        float m = fmaxf(t0, t1);
        #pragma unroll
        for (int o = 16; o > 0; o >>= 1)
            m = fmaxf(m, __shfl_xor_sync(0xffffffffu, m, o));
        if (lane == 0) sredM[warp] = m;
        __syncthreads();
        if (s < 16) {
            float mm = sredM[s];
            #pragma unroll
            for (int o = 8; o > 0; o >>= 1)
                mm = fmaxf(mm, __shfl_xor_sync(0xffffu, mm, o));
            if (s == 0) bc[0] = mm;
        }
        __syncthreads();
        float M = bc[0];

        // softmax weights + weighted feature sums (all f32)
        float p0 = ex2_approx((t0 - M) * LOG2E);
        float p1 = ex2_approx((t1 - M) * LOG2E);
        float a  = p0 + p1;
        float bx = fmaf(p0, x0l, p1 * x0h);
        float by = fmaf(p0, x1l, p1 * x1h);
        #pragma unroll
        for (int o = 16; o > 0; o >>= 1) {
            a  += __shfl_xor_sync(0xffffffffu, a,  o);
            bx += __shfl_xor_sync(0xffffffffu, bx, o);
            by += __shfl_xor_sync(0xffffffffu, by, o);
        }
        if (lane == 0) { sredP[warp] = a; sredX[warp] = bx; sredY[warp] = by; }
        __syncthreads();
        if (s < 16) {
            float aa = sredP[s], xx = sredX[s], yy = sredY[s];
            #pragma unroll
            for (int o = 8; o > 0; o >>= 1) {
                aa += __shfl_xor_sync(0xffffu, aa, o);
                xx += __shfl_xor_sync(0xffffu, xx, o);
                yy += __shfl_xor_sync(0xffffu, yy, o);
            }
            if (s == 0) { bc[1] = aa; bc[2] = xx; bc[3] = yy; }
        }
        __syncthreads();
        float inv = 1.f / bc[1];
        z0 = bc[2] * inv;   // xbar0
        z1 = bc[3] * inv;   // xbar1
    }

    // Output MLP (folded through sw), f32
    if (s == 0) {
        float o = fc2_b[0];
        #pragma unroll
        for (int j = 0; j < NFC; j++) {
            float hv = fmaf(gF[j].x, z0, fmaf(gF[j].y, z1, gfb[j]));
            hv = fmaxf(hv, 0.f);
            o = fmaf(fc2_w[j], hv, o);
        }
        out[b] = o;
    }
}

extern "C" void kernel_launch(void* const* d_in, const int* in_sizes, int n_in,
                              void* d_out, int out_size)
{
    const float* stat   = (const float*)d_in[0];   // [256, 2, 1024]
    const float* dyn    = (const float*)d_in[1];   // [256, 2, 1024]
    const float* istate = (const float*)d_in[2];   // [256, 2]
    const float* sw     = (const float*)d_in[3];   // [256, 2]
    const float* sb     = (const float*)d_in[4];   // [256]
    const float* dw     = (const float*)d_in[5];   // [256, 2]
    const float* db     = (const float*)d_in[6];   // [256]
    const float* v      = (const float*)d_in[7];   // [1, 256]
    const float* W      = (const float*)d_in[8];   // [256, 768]
    const float* fc1_w  = (const float*)d_in[9];   // [20, 256]
    const float* fc1_b  = (const float*)d_in[10];  // [20]
    const float* fc2_w  = (const float*)d_in[11];  // [1, 20]
    const float* fc2_b  = (const float*)d_in[12];  // [1]
    float* out = (float*)d_out;                    // [256, 1]

    precompute_kernel<<<NH + NFC, 256>>>(sw, sb, dw, db, W, v, fc1_w, fc1_b);
    attn_kernel<<<NB, BT>>>(stat, dyn, istate, fc2_w, fc2_b, out);
}